// round 1
// baseline (speedup 1.0000x reference)
#include <cuda_runtime.h>
#include <cuda_bf16.h>
#include <math.h>

// Problem constants (fixed by the reference)
constexpr int NN = 50000;   // nodes
constexpr int EE = 800000;  // edges
constexpr int NF = 512;     // input features
constexpr int NH = 96;      // hidden
constexpr int NC = 64;      // classes
constexpr int NL = 8;       // layers
constexpr float ALPHA = 0.1f;

constexpr int GBLK = (NN + 63) / 64;  // 782 blocks of 64 rows

// ---------------- scratch (device globals; no allocations allowed) ----------
__device__ __align__(16) float g_h [NN * NH];
__device__ __align__(16) float g_x0[NN * NH];
__device__ __align__(16) float g_hc[NN * NH];
__device__ int g_deg[NN];
__device__ int g_rowptr[NN + 1];
__device__ int g_cursor[NN];
__device__ int g_esrc[EE];

// ---------------- CSR build ----------------
__global__ void k_zero_deg() {
    int i = blockIdx.x * blockDim.x + threadIdx.x;
    if (i < NN) g_deg[i] = 0;
}

__global__ void k_hist(const int* __restrict__ dst) {
    int e = blockIdx.x * blockDim.x + threadIdx.x;
    if (e < EE) atomicAdd(&g_deg[dst[e]], 1);
}

// single-block exclusive scan of g_deg -> g_rowptr (+ cursor copy)
__global__ void k_scan() {
    __shared__ int sm[1024];
    __shared__ int s_carry;
    int tid = threadIdx.x;
    if (tid == 0) s_carry = 0;
    __syncthreads();
    for (int base = 0; base < NN; base += 1024) {
        int i = base + tid;
        int v = (i < NN) ? g_deg[i] : 0;
        sm[tid] = v;
        __syncthreads();
        #pragma unroll
        for (int off = 1; off < 1024; off <<= 1) {
            int t = (tid >= off) ? sm[tid - off] : 0;
            __syncthreads();
            sm[tid] += t;
            __syncthreads();
        }
        int excl = s_carry + sm[tid] - v;
        if (i < NN) { g_rowptr[i] = excl; g_cursor[i] = excl; }
        __syncthreads();
        if (tid == 0) s_carry += sm[1023];
        __syncthreads();
    }
    if (tid == 0) g_rowptr[NN] = s_carry;
}

__global__ void k_fill(const int* __restrict__ src, const int* __restrict__ dst) {
    int e = blockIdx.x * blockDim.x + threadIdx.x;
    if (e < EE) {
        int pos = atomicAdd(&g_cursor[dst[e]], 1);
        g_esrc[pos] = src[e];
    }
}

// ---------------- input GEMM: h = relu(x @ W_in + b_in); also x0 = h -------
// M=50000, K=512, N=96. BM=64, BK=64, BN=96. 256 threads, 4x6 per thread.
__global__ void k_gemm_in(const float* __restrict__ x,
                          const float* __restrict__ W,
                          const float* __restrict__ b) {
    __shared__ float As[64][64];   // 16 KB
    __shared__ float Bs[64][96];   // 24 KB
    int tid = threadIdx.x;
    int rg = tid >> 4, cg = tid & 15;
    int row0 = blockIdx.x * 64;

    float acc[4][6];
    #pragma unroll
    for (int i = 0; i < 4; i++)
        #pragma unroll
        for (int j = 0; j < 6; j++) acc[i][j] = 0.f;

    for (int kb = 0; kb < NF / 64; kb++) {
        // A tile: 64x64 = 1024 float4, 4 per thread
        #pragma unroll
        for (int t = 0; t < 4; t++) {
            int idx = tid + t * 256;
            int r = idx >> 4, c4 = idx & 15;
            float4 v = make_float4(0.f, 0.f, 0.f, 0.f);
            int row = row0 + r;
            if (row < NN)
                v = ((const float4*)x)[row * (NF / 4) + kb * 16 + c4];
            *(float4*)&As[r][c4 * 4] = v;
        }
        // B tile: 64x96 = 1536 float4, 6 per thread
        #pragma unroll
        for (int t = 0; t < 6; t++) {
            int idx = tid + t * 256;
            int k = idx / 24, c4 = idx % 24;
            *(float4*)&Bs[k][c4 * 4] =
                ((const float4*)W)[(kb * 64 + k) * (NH / 4) + c4];
        }
        __syncthreads();
        #pragma unroll 4
        for (int k = 0; k < 64; k++) {
            float a[4], bb[6];
            #pragma unroll
            for (int i = 0; i < 4; i++) a[i] = As[rg * 4 + i][k];
            #pragma unroll
            for (int j = 0; j < 6; j++) bb[j] = Bs[k][cg * 6 + j];
            #pragma unroll
            for (int i = 0; i < 4; i++)
                #pragma unroll
                for (int j = 0; j < 6; j++) acc[i][j] = fmaf(a[i], bb[j], acc[i][j]);
        }
        __syncthreads();
    }
    #pragma unroll
    for (int i = 0; i < 4; i++) {
        int row = row0 + rg * 4 + i;
        if (row >= NN) continue;
        #pragma unroll
        for (int j = 0; j < 6; j++) {
            int c = cg * 6 + j;
            float v = fmaxf(acc[i][j] + b[c], 0.f);
            g_h[row * NH + c]  = v;
            g_x0[row * NH + c] = v;
        }
    }
}

// ---------------- aggregation: hc = 0.9*segsum(h[src]->dst) + 0.1*x0 -------
// block = (96,4): 4 nodes/block, one thread per (node, feature)
__global__ void k_agg() {
    int f = threadIdx.x;                       // 0..95
    int node = blockIdx.x * 4 + threadIdx.y;
    int s = g_rowptr[node];
    int e = g_rowptr[node + 1];
    float acc = 0.f;
    int i = s;
    for (; i + 4 <= e; i += 4) {
        int s0 = g_esrc[i], s1 = g_esrc[i + 1], s2 = g_esrc[i + 2], s3 = g_esrc[i + 3];
        float v0 = g_h[s0 * NH + f];
        float v1 = g_h[s1 * NH + f];
        float v2 = g_h[s2 * NH + f];
        float v3 = g_h[s3 * NH + f];
        acc += (v0 + v1) + (v2 + v3);
    }
    for (; i < e; i++) acc += g_h[g_esrc[i] * NH + f];
    g_hc[node * NH + f] = (1.f - ALPHA) * acc + ALPHA * g_x0[node * NH + f];
}

// ---------------- layer GEMM: h = relu((1-b)*hc + b*(hc @ W)) --------------
// M=50000, K=96, N=96. BM=64. dynamic smem: As 64x96 + Ws 96x96 = 60 KB
__global__ void k_layer(const float* __restrict__ W, float beta) {
    extern __shared__ float sm[];
    float* As = sm;               // 64*96
    float* Ws = sm + 64 * NH;     // 96*96
    int tid = threadIdx.x;
    int rg = tid >> 4, cg = tid & 15;
    int row0 = blockIdx.x * 64;

    // load W: 9216 floats = 2304 float4, 9 per thread
    #pragma unroll
    for (int t = 0; t < 9; t++) {
        int idx = tid + t * 256;
        ((float4*)Ws)[idx] = ((const float4*)W)[idx];
    }
    // load hc tile: 6144 floats = 1536 float4, 6 per thread
    #pragma unroll
    for (int t = 0; t < 6; t++) {
        int idx = tid + t * 256;
        int r = idx / 24, c4 = idx % 24;
        float4 v = make_float4(0.f, 0.f, 0.f, 0.f);
        int row = row0 + r;
        if (row < NN) v = ((const float4*)g_hc)[row * 24 + c4];
        ((float4*)As)[idx] = v;
    }
    __syncthreads();

    float acc[4][6];
    #pragma unroll
    for (int i = 0; i < 4; i++)
        #pragma unroll
        for (int j = 0; j < 6; j++) acc[i][j] = 0.f;

    #pragma unroll 4
    for (int k = 0; k < NH; k++) {
        float a[4], bb[6];
        #pragma unroll
        for (int i = 0; i < 4; i++) a[i] = As[(rg * 4 + i) * NH + k];
        #pragma unroll
        for (int j = 0; j < 6; j++) bb[j] = Ws[k * NH + cg * 6 + j];
        #pragma unroll
        for (int i = 0; i < 4; i++)
            #pragma unroll
            for (int j = 0; j < 6; j++) acc[i][j] = fmaf(a[i], bb[j], acc[i][j]);
    }

    float ob = 1.f - beta;
    #pragma unroll
    for (int i = 0; i < 4; i++) {
        int row = row0 + rg * 4 + i;
        if (row >= NN) continue;
        #pragma unroll
        for (int j = 0; j < 6; j++) {
            int c = cg * 6 + j;
            float hcv = As[(rg * 4 + i) * NH + c];
            g_h[row * NH + c] = fmaxf(ob * hcv + beta * acc[i][j], 0.f);
        }
    }
}

// ---------------- output GEMM + log-softmax --------------------------------
// M=50000, K=96, N=64. BM=64. 256 threads, 4x4 per thread. 48 KB dyn smem.
__global__ void k_out(const float* __restrict__ W,
                      const float* __restrict__ b,
                      float* __restrict__ out) {
    extern __shared__ float sm[];
    float* As = sm;               // 64*96
    float* Ws = sm + 64 * NH;     // 96*64
    int tid = threadIdx.x;
    int rg = tid >> 4, cg = tid & 15;
    int row0 = blockIdx.x * 64;

    // W_out: 6144 floats = 1536 float4, 6 per thread
    #pragma unroll
    for (int t = 0; t < 6; t++) {
        int idx = tid + t * 256;
        ((float4*)Ws)[idx] = ((const float4*)W)[idx];
    }
    // h tile
    #pragma unroll
    for (int t = 0; t < 6; t++) {
        int idx = tid + t * 256;
        int r = idx / 24, c4 = idx % 24;
        float4 v = make_float4(0.f, 0.f, 0.f, 0.f);
        int row = row0 + r;
        if (row < NN) v = ((const float4*)g_h)[row * 24 + c4];
        ((float4*)As)[idx] = v;
    }
    __syncthreads();

    float acc[4][4];
    #pragma unroll
    for (int i = 0; i < 4; i++)
        #pragma unroll
        for (int j = 0; j < 4; j++) acc[i][j] = 0.f;

    #pragma unroll 4
    for (int k = 0; k < NH; k++) {
        float a[4], bb[4];
        #pragma unroll
        for (int i = 0; i < 4; i++) a[i] = As[(rg * 4 + i) * NH + k];
        #pragma unroll
        for (int j = 0; j < 4; j++) bb[j] = Ws[k * NC + cg * 4 + j];
        #pragma unroll
        for (int i = 0; i < 4; i++)
            #pragma unroll
            for (int j = 0; j < 4; j++) acc[i][j] = fmaf(a[i], bb[j], acc[i][j]);
    }

    // bias
    #pragma unroll
    for (int i = 0; i < 4; i++)
        #pragma unroll
        for (int j = 0; j < 4; j++) acc[i][j] += b[cg * 4 + j];

    // log-softmax: the 16 cg lanes of a row live in one warp half -> width-16 shfl
    #pragma unroll
    for (int i = 0; i < 4; i++) {
        float m = fmaxf(fmaxf(acc[i][0], acc[i][1]), fmaxf(acc[i][2], acc[i][3]));
        #pragma unroll
        for (int off = 8; off >= 1; off >>= 1)
            m = fmaxf(m, __shfl_xor_sync(0xffffffffu, m, off, 16));
        float s = __expf(acc[i][0] - m) + __expf(acc[i][1] - m)
                + __expf(acc[i][2] - m) + __expf(acc[i][3] - m);
        #pragma unroll
        for (int off = 8; off >= 1; off >>= 1)
            s += __shfl_xor_sync(0xffffffffu, s, off, 16);
        float lse = m + logf(s);
        int row = row0 + rg * 4 + i;
        if (row < NN) {
            #pragma unroll
            for (int j = 0; j < 4; j++)
                out[row * NC + cg * 4 + j] = acc[i][j] - lse;
        }
    }
}

// ---------------- launch ----------------------------------------------------
extern "C" void kernel_launch(void* const* d_in, const int* in_sizes, int n_in,
                              void* d_out, int out_size) {
    const float* x      = (const float*)d_in[0];
    const int*   ei     = (const int*)  d_in[1];
    const float* W_in   = (const float*)d_in[2];
    const float* b_in   = (const float*)d_in[3];
    const float* conv_W = (const float*)d_in[4];
    const float* W_out  = (const float*)d_in[5];
    const float* b_out  = (const float*)d_in[6];
    float* out = (float*)d_out;

    const int* src = ei;        // edge_index[0]
    const int* dst = ei + EE;   // edge_index[1]

    const int LAYER_SMEM = (64 * NH + NH * NH) * 4;   // 61440
    const int OUT_SMEM   = (64 * NH + NH * NC) * 4;   // 49152
    cudaFuncSetAttribute(k_layer, cudaFuncAttributeMaxDynamicSharedMemorySize, LAYER_SMEM);
    cudaFuncSetAttribute(k_out,   cudaFuncAttributeMaxDynamicSharedMemorySize, OUT_SMEM);

    // CSR build
    k_zero_deg<<<(NN + 255) / 256, 256>>>();
    k_hist<<<(EE + 255) / 256, 256>>>(dst);
    k_scan<<<1, 1024>>>();
    k_fill<<<(EE + 255) / 256, 256>>>(src, dst);

    // input projection
    k_gemm_in<<<GBLK, 256>>>(x, W_in, b_in);

    // 8 GCNII layers
    for (int l = 0; l < NL; l++) {
        float beta = (float)log(0.5 / (double)(l + 1) + 1.0);
        k_agg<<<NN / 4, dim3(96, 4)>>>();
        k_layer<<<GBLK, 256, LAYER_SMEM>>>(conv_W + (size_t)l * NH * NH, beta);
    }

    // output + log-softmax
    k_out<<<GBLK, 256, OUT_SMEM>>>(W_out, b_out, out);
}

// round 3
// speedup vs baseline: 1.5523x; 1.5523x over previous
#include <cuda_runtime.h>
#include <math.h>
#include <stdint.h>

constexpr int NN = 50000;   // nodes
constexpr int EE = 800000;  // edges
constexpr int NF = 512;     // input features
constexpr int NH = 96;      // hidden
constexpr int NC = 64;      // classes
constexpr int NL = 8;       // layers
constexpr float ALPHA = 0.1f;
constexpr int LDW = 100;    // padded leading dim for weight tiles (bank-conflict-free)

constexpr int GBLK128 = (NN + 127) / 128;   // 391
constexpr int GBLK64  = (NN + 63) / 64;     // 782

// ---------------- scratch (device globals; no allocations allowed) ----------
__device__ __align__(16) float g_h [NN * NH];
__device__ __align__(16) float g_x0[NN * NH];
__device__ __align__(16) float g_hc[NN * NH];
__device__ int g_deg[NN];
__device__ int g_rowptr[NN + 1];
__device__ int g_cursor[NN];
__device__ int g_esrc[EE];
// pre-converted / pre-split weights (tf32-valid fp32 bit patterns), padded to LDW
__device__ __align__(16) float g_Wih[NF * LDW];
__device__ __align__(16) float g_Wil[NF * LDW];
__device__ __align__(16) float g_Wm [NL * NH * LDW];

// ---------------- tf32 helpers ----------------
__device__ __forceinline__ uint32_t f2tf(float f) {
    uint32_t u;
    asm("cvt.rna.tf32.f32 %0, %1;" : "=r"(u) : "f"(f));
    return u;
}

__device__ __forceinline__ void mma8(float* c, const uint32_t* a, const uint32_t* b) {
    asm volatile(
        "mma.sync.aligned.m16n8k8.row.col.f32.tf32.tf32.f32 "
        "{%0,%1,%2,%3}, {%4,%5,%6,%7}, {%8,%9}, {%0,%1,%2,%3};"
        : "+f"(c[0]), "+f"(c[1]), "+f"(c[2]), "+f"(c[3])
        : "r"(a[0]), "r"(a[1]), "r"(a[2]), "r"(a[3]), "r"(b[0]), "r"(b[1]));
}

// ---------------- weight prep ----------------
__global__ void k_prep_in(const float* __restrict__ W) {
    int idx = blockIdx.x * blockDim.x + threadIdx.x;
    if (idx >= NF * LDW) return;
    int k = idx / LDW, n = idx % LDW;
    float hi = 0.f, lo = 0.f;
    if (n < NH) {
        float w = W[k * NH + n];
        uint32_t h = f2tf(w);
        hi = __uint_as_float(h);
        lo = __uint_as_float(f2tf(w - hi));
    }
    g_Wih[idx] = hi;
    g_Wil[idx] = lo;
}

__global__ void k_prep_wm(const float* __restrict__ convW) {
    int idx = blockIdx.x * blockDim.x + threadIdx.x;
    if (idx >= NL * NH * LDW) return;
    int l = idx / (NH * LDW);
    int r = (idx / LDW) % NH;
    int n = idx % LDW;
    float v = 0.f;
    if (n < NH) v = __uint_as_float(f2tf(convW[l * NH * NH + r * NH + n]));
    g_Wm[idx] = v;
}

// ---------------- CSR build ----------------
__global__ void k_zero_deg() {
    int i = blockIdx.x * blockDim.x + threadIdx.x;
    if (i < NN) g_deg[i] = 0;
}

__global__ void k_hist(const int* __restrict__ dst) {
    int e = blockIdx.x * blockDim.x + threadIdx.x;
    if (e < EE) atomicAdd(&g_deg[dst[e]], 1);
}

__global__ void k_scan() {
    __shared__ int wsum[32];
    __shared__ int carry;
    int tid = threadIdx.x, lane = tid & 31, wid = tid >> 5;
    if (tid == 0) carry = 0;
    __syncthreads();
    for (int base = 0; base < NN; base += 1024) {
        int i = base + tid;
        int v = (i < NN) ? g_deg[i] : 0;
        int x = v;
        #pragma unroll
        for (int o = 1; o < 32; o <<= 1) {
            int t = __shfl_up_sync(0xffffffffu, x, o);
            if (lane >= o) x += t;
        }
        if (lane == 31) wsum[wid] = x;
        __syncthreads();
        if (wid == 0) {
            int w = wsum[lane];
            #pragma unroll
            for (int o = 1; o < 32; o <<= 1) {
                int t = __shfl_up_sync(0xffffffffu, w, o);
                if (lane >= o) w += t;
            }
            wsum[lane] = w;
        }
        __syncthreads();
        int wbase = wid ? wsum[wid - 1] : 0;
        int excl = carry + wbase + x - v;
        if (i < NN) { g_rowptr[i] = excl; g_cursor[i] = excl; }
        __syncthreads();
        if (tid == 0) carry += wsum[31];
        __syncthreads();
    }
    if (threadIdx.x == 0) g_rowptr[NN] = carry;
}

__global__ void k_fill(const int* __restrict__ src, const int* __restrict__ dst) {
    int e = blockIdx.x * blockDim.x + threadIdx.x;
    if (e < EE) {
        int pos = atomicAdd(&g_cursor[dst[e]], 1);
        g_esrc[pos] = src[e];
    }
}

// ---------------- input GEMM (3xtf32): h = x0 = relu(x @ W_in + b_in) ------
// block 256 thr (8 warps, 4Mx2N), tile 128x96, warp tile 32x48, K chunks of 32
__global__ void k_gemm_in(const float* __restrict__ x, const float* __restrict__ bias) {
    extern __shared__ float sm[];
    float* As = sm;                 // [128][36] raw fp32 activations
    float* Wh = sm + 128 * 36;      // [32][100]
    float* Wl = Wh + 32 * LDW;      // [32][100]
    int tid = threadIdx.x;
    int warp = tid >> 5, lane = tid & 31;
    int wm = warp >> 1, wn = warp & 1;
    int g = lane >> 2, q = lane & 3;
    int row0 = blockIdx.x * 128;

    float c[2][6][4];
    #pragma unroll
    for (int mt = 0; mt < 2; mt++)
        #pragma unroll
        for (int nt = 0; nt < 6; nt++)
            #pragma unroll
            for (int i = 0; i < 4; i++) c[mt][nt][i] = 0.f;

    for (int kb = 0; kb < NF / 32; kb++) {
        // A tile: 128x32 = 1024 float4
        #pragma unroll
        for (int t = 0; t < 4; t++) {
            int idx = tid + t * 256;
            int r = idx >> 3, c4 = idx & 7;
            float4 v = make_float4(0.f, 0.f, 0.f, 0.f);
            if (row0 + r < NN)
                v = ((const float4*)x)[(size_t)(row0 + r) * (NF / 4) + kb * 8 + c4];
            *(float4*)&As[r * 36 + c4 * 4] = v;
        }
        // W hi/lo tiles: 32x100 -> 800 float4 each
        #pragma unroll
        for (int t = 0; t < 4; t++) {
            int i = tid + t * 256;
            if (i < 800) {
                int r = i / 25, cc = i % 25;
                *(float4*)&Wh[r * LDW + cc * 4] = *(const float4*)&g_Wih[(kb * 32 + r) * LDW + cc * 4];
                *(float4*)&Wl[r * LDW + cc * 4] = *(const float4*)&g_Wil[(kb * 32 + r) * LDW + cc * 4];
            }
        }
        __syncthreads();

        #pragma unroll
        for (int ks = 0; ks < 4; ks++) {
            uint32_t ah[2][4], al[2][4], bh[6][2], bl[6][2];
            #pragma unroll
            for (int mt = 0; mt < 2; mt++) {
                int rbase = wm * 32 + mt * 16 + g;
                #pragma unroll
                for (int ii = 0; ii < 4; ii++) {
                    int rr = rbase + (ii & 1) * 8;
                    int kk = ks * 8 + q + (ii >> 1) * 4;
                    float a = As[rr * 36 + kk];
                    uint32_t hi = f2tf(a);
                    float lo = a - __uint_as_float(hi);
                    ah[mt][ii] = hi;
                    al[mt][ii] = f2tf(lo);
                }
            }
            #pragma unroll
            for (int nt = 0; nt < 6; nt++) {
                int ncol = wn * 48 + nt * 8 + g;
                int k0 = ks * 8 + q;
                bh[nt][0] = __float_as_uint(Wh[k0 * LDW + ncol]);
                bh[nt][1] = __float_as_uint(Wh[(k0 + 4) * LDW + ncol]);
                bl[nt][0] = __float_as_uint(Wl[k0 * LDW + ncol]);
                bl[nt][1] = __float_as_uint(Wl[(k0 + 4) * LDW + ncol]);
            }
            #pragma unroll
            for (int mt = 0; mt < 2; mt++)
                #pragma unroll
                for (int nt = 0; nt < 6; nt++) {
                    mma8(c[mt][nt], ah[mt], bh[nt]);
                    mma8(c[mt][nt], ah[mt], bl[nt]);
                    mma8(c[mt][nt], al[mt], bh[nt]);
                }
        }
        __syncthreads();
    }

    // epilogue: bias + relu -> g_h, g_x0
    #pragma unroll
    for (int mt = 0; mt < 2; mt++) {
        #pragma unroll
        for (int nt = 0; nt < 6; nt++) {
            int col = wn * 48 + nt * 8 + 2 * q;
            float b0 = bias[col], b1 = bias[col + 1];
            int r0 = row0 + wm * 32 + mt * 16 + g;
            if (r0 < NN) {
                float2 v;
                v.x = fmaxf(c[mt][nt][0] + b0, 0.f);
                v.y = fmaxf(c[mt][nt][1] + b1, 0.f);
                *(float2*)&g_h [r0 * NH + col] = v;
                *(float2*)&g_x0[r0 * NH + col] = v;
            }
            int r1 = r0 + 8;
            if (r1 < NN) {
                float2 v;
                v.x = fmaxf(c[mt][nt][2] + b0, 0.f);
                v.y = fmaxf(c[mt][nt][3] + b1, 0.f);
                *(float2*)&g_h [r1 * NH + col] = v;
                *(float2*)&g_x0[r1 * NH + col] = v;
            }
        }
    }
}

// ---------------- aggregation: hc = 0.9*segsum(h[src]->dst) + 0.1*x0 -------
// one warp per node; lanes 0..23 each own a float4 (4 features)
__global__ void k_agg() {
    int gw = (blockIdx.x * 256 + threadIdx.x) >> 5;
    int lane = threadIdx.x & 31;
    if (gw >= NN) return;
    int s = g_rowptr[gw];
    int e = g_rowptr[gw + 1];
    if (lane >= 24) return;
    const float4* __restrict__ h4 = (const float4*)g_h;
    float4 acc = make_float4(0.f, 0.f, 0.f, 0.f);
    int i = s;
    for (; i + 4 <= e; i += 4) {
        int s0 = g_esrc[i], s1 = g_esrc[i + 1], s2 = g_esrc[i + 2], s3 = g_esrc[i + 3];
        float4 v0 = h4[s0 * 24 + lane];
        float4 v1 = h4[s1 * 24 + lane];
        float4 v2 = h4[s2 * 24 + lane];
        float4 v3 = h4[s3 * 24 + lane];
        acc.x += (v0.x + v1.x) + (v2.x + v3.x);
        acc.y += (v0.y + v1.y) + (v2.y + v3.y);
        acc.z += (v0.z + v1.z) + (v2.z + v3.z);
        acc.w += (v0.w + v1.w) + (v2.w + v3.w);
    }
    for (; i < e; i++) {
        float4 v = h4[g_esrc[i] * 24 + lane];
        acc.x += v.x; acc.y += v.y; acc.z += v.z; acc.w += v.w;
    }
    float4 x0v = ((const float4*)g_x0)[gw * 24 + lane];
    float4 hc;
    const float OA = 1.0f - ALPHA;
    hc.x = OA * acc.x + ALPHA * x0v.x;
    hc.y = OA * acc.y + ALPHA * x0v.y;
    hc.z = OA * acc.z + ALPHA * x0v.z;
    hc.w = OA * acc.w + ALPHA * x0v.w;
    ((float4*)g_hc)[gw * 24 + lane] = hc;
}

// ---------------- layer GEMM (1xtf32 on beta term): ------------------------
// h = relu((1-b)*hc + b*(hc @ W)); residual term stays exact fp32 (from smem)
__global__ void k_layer(int l, float beta) {
    extern __shared__ float sm[];
    float* As = sm;                 // [128][100] raw fp32 hc
    float* Ws = sm + 128 * LDW;     // [96][100] tf32-valid W
    int tid = threadIdx.x;
    int warp = tid >> 5, lane = tid & 31;
    int wm = warp >> 1, wn = warp & 1;
    int g = lane >> 2, q = lane & 3;
    int row0 = blockIdx.x * 128;

    // load hc tile: 128x96 -> 3072 float4
    #pragma unroll
    for (int t = 0; t < 12; t++) {
        int i = tid + t * 256;
        int r = i / 24, cc = i % 24;
        float4 v = make_float4(0.f, 0.f, 0.f, 0.f);
        if (row0 + r < NN) v = ((const float4*)g_hc)[(row0 + r) * 24 + cc];
        *(float4*)&As[r * LDW + cc * 4] = v;
    }
    // load W: 96x100 -> 2400 float4
    const float* Wg = g_Wm + (size_t)l * NH * LDW;
    #pragma unroll
    for (int t = 0; t < 10; t++) {
        int i = tid + t * 256;
        if (i < 2400) {
            int r = i / 25, cc = i % 25;
            *(float4*)&Ws[r * LDW + cc * 4] = *(const float4*)&Wg[r * LDW + cc * 4];
        }
    }
    __syncthreads();

    float c[2][6][4];
    #pragma unroll
    for (int mt = 0; mt < 2; mt++)
        #pragma unroll
        for (int nt = 0; nt < 6; nt++)
            #pragma unroll
            for (int i = 0; i < 4; i++) c[mt][nt][i] = 0.f;

    #pragma unroll
    for (int ks = 0; ks < NH / 8; ks++) {
        uint32_t a[2][4], b[6][2];
        #pragma unroll
        for (int mt = 0; mt < 2; mt++) {
            int rbase = wm * 32 + mt * 16 + g;
            #pragma unroll
            for (int ii = 0; ii < 4; ii++) {
                int rr = rbase + (ii & 1) * 8;
                int kk = ks * 8 + q + (ii >> 1) * 4;
                a[mt][ii] = f2tf(As[rr * LDW + kk]);
            }
        }
        #pragma unroll
        for (int nt = 0; nt < 6; nt++) {
            int ncol = wn * 48 + nt * 8 + g;
            int k0 = ks * 8 + q;
            b[nt][0] = __float_as_uint(Ws[k0 * LDW + ncol]);
            b[nt][1] = __float_as_uint(Ws[(k0 + 4) * LDW + ncol]);
        }
        #pragma unroll
        for (int mt = 0; mt < 2; mt++)
            #pragma unroll
            for (int nt = 0; nt < 6; nt++)
                mma8(c[mt][nt], a[mt], b[nt]);
    }

    float ob = 1.f - beta;
    #pragma unroll
    for (int mt = 0; mt < 2; mt++) {
        #pragma unroll
        for (int nt = 0; nt < 6; nt++) {
            int col = wn * 48 + nt * 8 + 2 * q;
            int rl0 = wm * 32 + mt * 16 + g;
            int r0 = row0 + rl0;
            if (r0 < NN) {
                float hc0 = As[rl0 * LDW + col];
                float hc1 = As[rl0 * LDW + col + 1];
                float2 v;
                v.x = fmaxf(ob * hc0 + beta * c[mt][nt][0], 0.f);
                v.y = fmaxf(ob * hc1 + beta * c[mt][nt][1], 0.f);
                *(float2*)&g_h[r0 * NH + col] = v;
            }
            int rl1 = rl0 + 8;
            int r1 = r0 + 8;
            if (r1 < NN) {
                float hc0 = As[rl1 * LDW + col];
                float hc1 = As[rl1 * LDW + col + 1];
                float2 v;
                v.x = fmaxf(ob * hc0 + beta * c[mt][nt][2], 0.f);
                v.y = fmaxf(ob * hc1 + beta * c[mt][nt][3], 0.f);
                *(float2*)&g_h[r1 * NH + col] = v;
            }
        }
    }
}

// ---------------- output GEMM + log-softmax (fp32 FFMA) --------------------
__global__ void k_out(const float* __restrict__ W,
                      const float* __restrict__ b,
                      float* __restrict__ out) {
    extern __shared__ float sm[];
    float* As = sm;               // 64*96
    float* Ws = sm + 64 * NH;     // 96*64
    int tid = threadIdx.x;
    int rg = tid >> 4, cg = tid & 15;
    int row0 = blockIdx.x * 64;

    #pragma unroll
    for (int t = 0; t < 6; t++) {
        int idx = tid + t * 256;
        ((float4*)Ws)[idx] = ((const float4*)W)[idx];
    }
    #pragma unroll
    for (int t = 0; t < 6; t++) {
        int idx = tid + t * 256;
        int r = idx / 24, c4 = idx % 24;
        float4 v = make_float4(0.f, 0.f, 0.f, 0.f);
        int row = row0 + r;
        if (row < NN) v = ((const float4*)g_h)[row * 24 + c4];
        ((float4*)As)[idx] = v;
    }
    __syncthreads();

    float acc[4][4];
    #pragma unroll
    for (int i = 0; i < 4; i++)
        #pragma unroll
        for (int j = 0; j < 4; j++) acc[i][j] = 0.f;

    #pragma unroll 4
    for (int k = 0; k < NH; k++) {
        float a[4], bb[4];
        #pragma unroll
        for (int i = 0; i < 4; i++) a[i] = As[(rg * 4 + i) * NH + k];
        #pragma unroll
        for (int j = 0; j < 4; j++) bb[j] = Ws[k * NC + cg * 4 + j];
        #pragma unroll
        for (int i = 0; i < 4; i++)
            #pragma unroll
            for (int j = 0; j < 4; j++) acc[i][j] = fmaf(a[i], bb[j], acc[i][j]);
    }

    #pragma unroll
    for (int i = 0; i < 4; i++)
        #pragma unroll
        for (int j = 0; j < 4; j++) acc[i][j] += b[cg * 4 + j];

    #pragma unroll
    for (int i = 0; i < 4; i++) {
        float m = fmaxf(fmaxf(acc[i][0], acc[i][1]), fmaxf(acc[i][2], acc[i][3]));
        #pragma unroll
        for (int off = 8; off >= 1; off >>= 1)
            m = fmaxf(m, __shfl_xor_sync(0xffffffffu, m, off, 16));
        float s = __expf(acc[i][0] - m) + __expf(acc[i][1] - m)
                + __expf(acc[i][2] - m) + __expf(acc[i][3] - m);
        #pragma unroll
        for (int off = 8; off >= 1; off >>= 1)
            s += __shfl_xor_sync(0xffffffffu, s, off, 16);
        float lse = m + logf(s);
        int row = row0 + rg * 4 + i;
        if (row < NN) {
            #pragma unroll
            for (int j = 0; j < 4; j++)
                out[row * NC + cg * 4 + j] = acc[i][j] - lse;
        }
    }
}

// ---------------- launch ----------------------------------------------------
extern "C" void kernel_launch(void* const* d_in, const int* in_sizes, int n_in,
                              void* d_out, int out_size) {
    const float* x      = (const float*)d_in[0];
    const int*   ei     = (const int*)  d_in[1];
    const float* W_in   = (const float*)d_in[2];
    const float* b_in   = (const float*)d_in[3];
    const float* conv_W = (const float*)d_in[4];
    const float* W_out  = (const float*)d_in[5];
    const float* b_out  = (const float*)d_in[6];
    float* out = (float*)d_out;

    const int* src = ei;        // edge_index[0]
    const int* dst = ei + EE;   // edge_index[1]

    const int IN_SMEM    = (128 * 36 + 2 * 32 * LDW) * 4;   // 44032
    const int LAYER_SMEM = (128 * LDW + NH * LDW) * 4;      // 89600
    const int OUT_SMEM   = (64 * NH + NH * NC) * 4;         // 49152
    cudaFuncSetAttribute(k_gemm_in, cudaFuncAttributeMaxDynamicSharedMemorySize, IN_SMEM);
    cudaFuncSetAttribute(k_layer,   cudaFuncAttributeMaxDynamicSharedMemorySize, LAYER_SMEM);
    cudaFuncSetAttribute(k_out,     cudaFuncAttributeMaxDynamicSharedMemorySize, OUT_SMEM);

    // weight prep (tf32 rounding / splitting)
    k_prep_in<<<(NF * LDW + 255) / 256, 256>>>(W_in);
    k_prep_wm<<<(NL * NH * LDW + 255) / 256, 256>>>(conv_W);

    // CSR build
    k_zero_deg<<<(NN + 255) / 256, 256>>>();
    k_hist<<<(EE + 255) / 256, 256>>>(dst);
    k_scan<<<1, 1024>>>();
    k_fill<<<(EE + 255) / 256, 256>>>(src, dst);

    // input projection
    k_gemm_in<<<GBLK128, 256, IN_SMEM>>>(x, b_in);

    // 8 GCNII layers
    for (int l = 0; l < NL; l++) {
        float beta = (float)log(0.5 / (double)(l + 1) + 1.0);
        k_agg<<<NN / 8, 256>>>();
        k_layer<<<GBLK128, 256, LAYER_SMEM>>>(l, beta);
    }

    // output + log-softmax
    k_out<<<GBLK64, 256, OUT_SMEM>>>(W_out, b_out, out);
}